// round 2
// baseline (speedup 1.0000x reference)
#include <cuda_runtime.h>
#include <math.h>

#define B_ 64
#define S_ 512
#define I_ 256
#define H_ 1024
#define O_ 256

// Scratch: [s][h][b] layout. pre written by GEMM, overwritten in place by
// hidden states during the recurrence (slot t read as pre at step t only).
__device__ float g_buf0[S_ * H_ * B_];
__device__ float g_buf1[S_ * H_ * B_];

// Grid barrier state (sense-reversal; gen monotonic across launches/replays,
// cnt returns to 0 at every barrier -> deterministic).
__device__ unsigned g_bar_cnt = 0;
__device__ unsigned g_bar_gen = 0;

typedef unsigned long long u64;

__device__ __forceinline__ u64 pack2(float x, float y) {
    u64 r; asm("mov.b64 %0,{%1,%2};" : "=l"(r) : "f"(x), "f"(y)); return r;
}
__device__ __forceinline__ u64 fma2(u64 a, u64 b, u64 c) {
    u64 d; asm("fma.rn.f32x2 %0,%1,%2,%3;" : "=l"(d) : "l"(a), "l"(b), "l"(c)); return d;
}
__device__ __forceinline__ float2 unpk(u64 v) {
    float2 f; asm("mov.b64 {%0,%1},%2;" : "=f"(f.x), "=f"(f.y) : "l"(v)); return f;
}

// ---------------------------------------------------------------------------
// Tiled fp32 GEMM, f32x2 microkernel.
//   C(s, n, b) = sum_k A(s,k,b) * W[n][k] + b1[n] (+ b2[n])
// Tile: 64 b (full batch) x 128 n, BK=32, 128 threads, 8x8 microtile.
// AKM=1: A is [s][k][b] scratch.  AKM=0: A is x [b][s][k], K = I_.
// OUTM=0: write [s][h][b] scratch.  OUTM=1: write final out [b][s][o].
// ---------------------------------------------------------------------------
template <int K, int AKM, int OUTM>
__global__ void __launch_bounds__(128) gemm_k(const float* __restrict__ A,
                                              const float* __restrict__ W,
                                              const float* __restrict__ b1,
                                              const float* __restrict__ b2,
                                              float* __restrict__ C) {
    __shared__ __align__(16) float sA[32][68];
    __shared__ __align__(16) float sB[32][132];

    const int s   = blockIdx.y;
    const int n0  = blockIdx.x * 128;
    const int tid = threadIdx.x;
    const int tm  = tid & 7;   // b-group: b = tm*8 + i
    const int tn  = tid >> 3;  // n-group: n = tn*8 + 2j + e

    u64 acc[8][4];
#pragma unroll
    for (int i = 0; i < 8; i++)
#pragma unroll
        for (int j = 0; j < 4; j++) acc[i][j] = 0ull;

    const float* Abase = AKM ? (A + (size_t)s * (H_ * B_)) : A;

    for (int kc = 0; kc < K; kc += 32) {
        if (AKM) {
#pragma unroll
            for (int i = 0; i < 4; i++) {
                int v = tid + i * 128;       // 0..511 float4s
                int k = v >> 4, b4 = v & 15;
                float4 f = __ldg((const float4*)(Abase + (size_t)(kc + k) * B_ + b4 * 4));
                *(float4*)&sA[k][b4 * 4] = f;
            }
        } else {
#pragma unroll
            for (int i = 0; i < 4; i++) {
                int v = tid + i * 128;
                int b = v >> 3, kq = v & 7;
                float4 f = __ldg((const float4*)(Abase + ((size_t)b * S_ + s) * I_ + kc + kq * 4));
                sA[kq * 4 + 0][b] = f.x;
                sA[kq * 4 + 1][b] = f.y;
                sA[kq * 4 + 2][b] = f.z;
                sA[kq * 4 + 3][b] = f.w;
            }
        }
#pragma unroll
        for (int i = 0; i < 8; i++) {
            int v = tid + i * 128;           // 0..1023 float4s
            int n = v >> 3, kq = v & 7;
            float4 f = __ldg((const float4*)(W + (size_t)(n0 + n) * K + kc + kq * 4));
            sB[kq * 4 + 0][n] = f.x;
            sB[kq * 4 + 1][n] = f.y;
            sB[kq * 4 + 2][n] = f.z;
            sB[kq * 4 + 3][n] = f.w;
        }
        __syncthreads();
#pragma unroll
        for (int k = 0; k < 32; k++) {
            float4 a0 = *(const float4*)&sA[k][tm * 8];
            float4 a1 = *(const float4*)&sA[k][tm * 8 + 4];
            ulonglong2 w01 = *(const ulonglong2*)&sB[k][tn * 8];
            ulonglong2 w23 = *(const ulonglong2*)&sB[k][tn * 8 + 4];
            float av[8] = {a0.x, a0.y, a0.z, a0.w, a1.x, a1.y, a1.z, a1.w};
#pragma unroll
            for (int i = 0; i < 8; i++) {
                u64 ai = pack2(av[i], av[i]);
                acc[i][0] = fma2(ai, w01.x, acc[i][0]);
                acc[i][1] = fma2(ai, w01.y, acc[i][1]);
                acc[i][2] = fma2(ai, w23.x, acc[i][2]);
                acc[i][3] = fma2(ai, w23.y, acc[i][3]);
            }
        }
        __syncthreads();
    }

    float bias[8];
#pragma unroll
    for (int j8 = 0; j8 < 8; j8++) {
        int n = n0 + tn * 8 + j8;
        bias[j8] = b1[n] + (b2 ? b2[n] : 0.0f);
    }

    if (OUTM == 0) {
        // [s][h][b]: per n, the thread's 8 b-values are contiguous -> float4 stores
        float* Cs = C + (size_t)s * (H_ * B_) + (size_t)(n0 + tn * 8) * B_ + tm * 8;
#pragma unroll
        for (int j = 0; j < 4; j++) {
            float v0[8], v1[8];
#pragma unroll
            for (int i = 0; i < 8; i++) {
                float2 t = unpk(acc[i][j]);
                v0[i] = t.x + bias[2 * j];
                v1[i] = t.y + bias[2 * j + 1];
            }
            *(float4*)(Cs + (size_t)(2 * j) * B_)       = make_float4(v0[0], v0[1], v0[2], v0[3]);
            *(float4*)(Cs + (size_t)(2 * j) * B_ + 4)   = make_float4(v0[4], v0[5], v0[6], v0[7]);
            *(float4*)(Cs + (size_t)(2 * j + 1) * B_)   = make_float4(v1[0], v1[1], v1[2], v1[3]);
            *(float4*)(Cs + (size_t)(2 * j + 1) * B_ + 4) = make_float4(v1[4], v1[5], v1[6], v1[7]);
        }
    } else {
        // out[b][s][o]: per b, the thread's 8 o-values are contiguous
#pragma unroll
        for (int i = 0; i < 8; i++) {
            int b = tm * 8 + i;
            float* Co = C + ((size_t)b * S_ + s) * O_ + n0 + tn * 8;
            float2 t0 = unpk(acc[i][0]), t1 = unpk(acc[i][1]);
            float2 t2 = unpk(acc[i][2]), t3 = unpk(acc[i][3]);
            *(float4*)Co       = make_float4(t0.x + bias[0], t0.y + bias[1],
                                             t1.x + bias[2], t1.y + bias[3]);
            *(float4*)(Co + 4) = make_float4(t2.x + bias[4], t2.y + bias[5],
                                             t3.x + bias[6], t3.y + bias[7]);
        }
    }
}

// ---------------------------------------------------------------------------
// Grid barrier (all CTAs co-resident: grid=128 <= 148 SMs, 1 CTA/SM fits)
// ---------------------------------------------------------------------------
__device__ __forceinline__ void grid_barrier(unsigned total) {
    __syncthreads();
    if (threadIdx.x == 0) {
        volatile unsigned* gen = &g_bar_gen;
        unsigned g0 = *gen;                    // snapshot BEFORE arriving
        __threadfence();                       // publish this CTA's stores
        unsigned old = atomicAdd(&g_bar_cnt, 1u);
        if (old == total - 1u) {
            g_bar_cnt = 0u;
            __threadfence();
            *gen = g0 + 1u;
        } else {
            while (*gen == g0) { __nanosleep(64); }
        }
        __threadfence();
    }
    __syncthreads();
}

// ---------------------------------------------------------------------------
// Persistent recurrence kernel: one full layer (512 steps).
// 128 CTAs x 256 threads. CTA owns 8 h-columns; its W_hh slice (8x1024,
// 32KB) stays in smem, stored k-major [k][8] for broadcast LDS.128.
// Thread: b = tid&63, g = tid>>6 owns k-range [g*256, g*256+256); K-split
// partials reduced through smem. h states read from buf via L2 (__ldcg —
// L1 may hold stale pre for these addresses), written in place over pre.
// ---------------------------------------------------------------------------
__global__ void __launch_bounds__(256) rnn_layer_kernel(const float* __restrict__ Whh,
                                                        float* __restrict__ buf,
                                                        unsigned nbar) {
    __shared__ __align__(16) float sW[H_ * 8];   // [k][j] 32 KB
    __shared__ float red[4][8][B_];              // 8 KB

    const int tid = threadIdx.x;
    const int n0  = blockIdx.x * 8;

    for (int v = tid; v < H_ * 8; v += 256) {
        int j = v >> 10, k = v & (H_ - 1);
        sW[k * 8 + j] = Whh[(size_t)(n0 + j) * H_ + k];
    }
    __syncthreads();

    const int b = tid & 63;
    const int g = tid >> 6;
    const float* wp = sW + g * 256 * 8;

    // t = 0: h_0 = tanh(pre_0)
    for (int o = tid; o < 512; o += 256) {
        int n = o >> 6, bb = o & 63;
        size_t idx = (size_t)(n0 + n) * B_ + bb;
        buf[idx] = tanhf(buf[idx]);
    }
    grid_barrier(nbar);

    for (int t = 1; t < S_; t++) {
        const float* hprev = buf + (size_t)(t - 1) * (H_ * B_) + (size_t)g * 256 * B_ + b;
        u64 acc0 = 0, acc1 = 0, acc2 = 0, acc3 = 0;

        float hb[8];
#pragma unroll
        for (int u = 0; u < 8; u++) hb[u] = __ldcg(hprev + (size_t)u * B_);

        for (int kc = 0; kc < 256; kc += 8) {
            float hn[8];
            if (kc + 8 < 256) {
#pragma unroll
                for (int u = 0; u < 8; u++)
                    hn[u] = __ldcg(hprev + (size_t)(kc + 8 + u) * B_);
            }
#pragma unroll
            for (int u = 0; u < 8; u++) {
                u64 ph = pack2(hb[u], hb[u]);
                ulonglong2 w0 = *(const ulonglong2*)(wp + (kc + u) * 8);
                ulonglong2 w1 = *(const ulonglong2*)(wp + (kc + u) * 8 + 4);
                acc0 = fma2(ph, w0.x, acc0);
                acc1 = fma2(ph, w0.y, acc1);
                acc2 = fma2(ph, w1.x, acc2);
                acc3 = fma2(ph, w1.y, acc3);
            }
            if (kc + 8 < 256) {
#pragma unroll
                for (int u = 0; u < 8; u++) hb[u] = hn[u];
            }
        }

        float2 a0 = unpk(acc0), a1 = unpk(acc1), a2 = unpk(acc2), a3 = unpk(acc3);
        red[g][0][b] = a0.x; red[g][1][b] = a0.y;
        red[g][2][b] = a1.x; red[g][3][b] = a1.y;
        red[g][4][b] = a2.x; red[g][5][b] = a2.y;
        red[g][6][b] = a3.x; red[g][7][b] = a3.y;
        __syncthreads();

        float* cur = buf + (size_t)t * (H_ * B_);
        for (int o = tid; o < 512; o += 256) {
            int n = o >> 6, bb = o & 63;
            float v = red[0][n][bb] + red[1][n][bb] + red[2][n][bb] + red[3][n][bb]
                    + cur[(size_t)(n0 + n) * B_ + bb];
            cur[(size_t)(n0 + n) * B_ + bb] = tanhf(v);
        }
        grid_barrier(nbar);   // includes __syncthreads guarding red reuse
    }
}

// ---------------------------------------------------------------------------

extern "C" void kernel_launch(void* const* d_in, const int* in_sizes, int n_in,
                              void* d_out, int out_size) {
    const float* x      = (const float*)d_in[0];
    const float* W_ih_0 = (const float*)d_in[1];
    const float* W_hh_0 = (const float*)d_in[2];
    const float* b_ih_0 = (const float*)d_in[3];
    const float* b_hh_0 = (const float*)d_in[4];
    const float* W_ih_1 = (const float*)d_in[5];
    const float* W_hh_1 = (const float*)d_in[6];
    const float* b_ih_1 = (const float*)d_in[7];
    const float* b_hh_1 = (const float*)d_in[8];
    const float* fc_w   = (const float*)d_in[9];
    const float* fc_b   = (const float*)d_in[10];
    float* out = (float*)d_out;

    float *buf0, *buf1;
    cudaGetSymbolAddress((void**)&buf0, g_buf0);
    cudaGetSymbolAddress((void**)&buf1, g_buf1);

    // 1. pre0[s][h][b] = x @ W_ih_0^T + (b_ih_0 + b_hh_0)
    gemm_k<I_, 0, 0><<<dim3(H_ / 128, S_), 128>>>(x, W_ih_0, b_ih_0, b_hh_0, buf0);
    // 2. layer-0 recurrence (in place)
    rnn_layer_kernel<<<128, 256>>>(W_hh_0, buf0, 128u);
    // 3. pre1[s][h][b] = hs0 @ W_ih_1^T + (b_ih_1 + b_hh_1)
    gemm_k<H_, 1, 0><<<dim3(H_ / 128, S_), 128>>>(buf0, W_ih_1, b_ih_1, b_hh_1, buf1);
    // 4. layer-1 recurrence (in place)
    rnn_layer_kernel<<<128, 256>>>(W_hh_1, buf1, 128u);
    // 5. out[b][s][o] = hs1 @ fc_w^T + fc_b
    gemm_k<H_, 1, 1><<<dim3(O_ / 128, S_), 128>>>(buf1, fc_w, fc_b, nullptr, out);
}

// round 3
// speedup vs baseline: 1.6139x; 1.6139x over previous
#include <cuda_runtime.h>
#include <math.h>

#define B_ 64
#define S_ 512
#define I_ 256
#define H_ 1024
#define O_ 256

// Unified scratch layout [s][b][h]. pre written by GEMM, overwritten in place
// by hidden states during the recurrence.
__device__ float g_buf0[S_ * B_ * H_];
__device__ float g_buf1[S_ * B_ * H_];
// Per-(layer, t, bgroup) completion counters (monotonic within a launch,
// zeroed by zero_flags at the start of every launch -> deterministic).
__device__ int g_flags[2 * S_ * 4];

typedef unsigned long long u64;

__device__ __forceinline__ u64 pack2(float x, float y) {
    u64 r; asm("mov.b64 %0,{%1,%2};" : "=l"(r) : "f"(x), "f"(y)); return r;
}
__device__ __forceinline__ u64 fma2(u64 a, u64 b, u64 c) {
    u64 d; asm("fma.rn.f32x2 %0,%1,%2,%3;" : "=l"(d) : "l"(a), "l"(b), "l"(c)); return d;
}
__device__ __forceinline__ u64 add2(u64 a, u64 b) {
    u64 d; asm("add.rn.f32x2 %0,%1,%2;" : "=l"(d) : "l"(a), "l"(b)); return d;
}
__device__ __forceinline__ float2 unpk(u64 v) {
    float2 f; asm("mov.b64 {%0,%1},%2;" : "=f"(f.x), "=f"(f.y) : "l"(v)); return f;
}
__device__ __forceinline__ void cpasync16(float* sdst, const float* gsrc) {
    unsigned sa = (unsigned)__cvta_generic_to_shared(sdst);
    asm volatile("cp.async.cg.shared.global [%0], [%1], 16;" :: "r"(sa), "l"(gsrc));
}
__device__ __forceinline__ int ld_cg_i(const int* p) {
    int v; asm volatile("ld.global.cg.b32 %0, [%1];" : "=r"(v) : "l"(p)); return v;
}

__global__ void zero_flags_k(int* f) { f[blockIdx.x * 1024 + threadIdx.x] = 0; }

// ---------------------------------------------------------------------------
// Tiled fp32 GEMM, f32x2 microkernel. C(row(b,s), n) = sum_k A(row,k)*W[n][k]+b
// 64 b (full batch) x 128 n tile, BK=32, 128 threads, 8x8 microtile.
// AROW=0: A row = b*S+s (x [b][s][k]). AROW=1: A row = s*64+b (buf [s][b][h]).
// CROW=0: C row = s*64+b, width H_ (buf). CROW=1: C row = b*S+s, width O_.
// ---------------------------------------------------------------------------
template <int K, int AROW, int CROW>
__global__ void __launch_bounds__(128) gemm_k(const float* __restrict__ A,
                                              const float* __restrict__ W,
                                              const float* __restrict__ b1,
                                              const float* __restrict__ b2,
                                              float* __restrict__ C) {
    __shared__ __align__(16) float sA[32][68];
    __shared__ __align__(16) float sB[32][132];

    const int s   = blockIdx.y;
    const int n0  = blockIdx.x * 128;
    const int tid = threadIdx.x;
    const int tm  = tid & 7;
    const int tn  = tid >> 3;

    u64 acc[8][4];
#pragma unroll
    for (int i = 0; i < 8; i++)
#pragma unroll
        for (int j = 0; j < 4; j++) acc[i][j] = 0ull;

    for (int kc = 0; kc < K; kc += 32) {
#pragma unroll
        for (int i = 0; i < 4; i++) {
            int v = tid + i * 128;
            int b = v >> 3, kq = v & 7;
            size_t row = AROW ? ((size_t)s * B_ + b) : ((size_t)b * S_ + s);
            float4 f = __ldg((const float4*)(A + row * K + kc + kq * 4));
            sA[kq * 4 + 0][b] = f.x;
            sA[kq * 4 + 1][b] = f.y;
            sA[kq * 4 + 2][b] = f.z;
            sA[kq * 4 + 3][b] = f.w;
        }
#pragma unroll
        for (int i = 0; i < 8; i++) {
            int v = tid + i * 128;
            int n = v >> 3, kq = v & 7;
            float4 f = __ldg((const float4*)(W + (size_t)(n0 + n) * K + kc + kq * 4));
            sB[kq * 4 + 0][n] = f.x;
            sB[kq * 4 + 1][n] = f.y;
            sB[kq * 4 + 2][n] = f.z;
            sB[kq * 4 + 3][n] = f.w;
        }
        __syncthreads();
#pragma unroll
        for (int k = 0; k < 32; k++) {
            float4 a0 = *(const float4*)&sA[k][tm * 8];
            float4 a1 = *(const float4*)&sA[k][tm * 8 + 4];
            ulonglong2 w01 = *(const ulonglong2*)&sB[k][tn * 8];
            ulonglong2 w23 = *(const ulonglong2*)&sB[k][tn * 8 + 4];
            float av[8] = {a0.x, a0.y, a0.z, a0.w, a1.x, a1.y, a1.z, a1.w};
#pragma unroll
            for (int i = 0; i < 8; i++) {
                u64 ai = pack2(av[i], av[i]);
                acc[i][0] = fma2(ai, w01.x, acc[i][0]);
                acc[i][1] = fma2(ai, w01.y, acc[i][1]);
                acc[i][2] = fma2(ai, w23.x, acc[i][2]);
                acc[i][3] = fma2(ai, w23.y, acc[i][3]);
            }
        }
        __syncthreads();
    }

    float bias[8];
#pragma unroll
    for (int j8 = 0; j8 < 8; j8++) {
        int n = n0 + tn * 8 + j8;
        bias[j8] = b1[n] + (b2 ? b2[n] : 0.0f);
    }

    const int NC = CROW ? O_ : H_;
#pragma unroll
    for (int i = 0; i < 8; i++) {
        int b = tm * 8 + i;
        size_t row = CROW ? ((size_t)b * S_ + s) : ((size_t)s * B_ + b);
        float* Co = C + row * NC + n0 + tn * 8;
        float2 t0 = unpk(acc[i][0]), t1 = unpk(acc[i][1]);
        float2 t2 = unpk(acc[i][2]), t3 = unpk(acc[i][3]);
        *(float4*)Co       = make_float4(t0.x + bias[0], t0.y + bias[1],
                                         t1.x + bias[2], t1.y + bias[3]);
        *(float4*)(Co + 4) = make_float4(t2.x + bias[4], t2.y + bias[5],
                                         t3.x + bias[6], t3.y + bias[7]);
    }
}

// ---------------------------------------------------------------------------
// Recurrence: grid 128 = 32 n-groups x 4 b-groups. CTA owns 32 n x 16 b.
// 512 threads = 16 warps: warp = kg*4 + ng4 (kg: k-group of 256, ng4: 8 n).
// Lane: bb = lane&15 (local b), kh = lane>>4 (k-half of 128 within kg).
// W slice (32 n x 1024 k, 128KB) resident in smem k-major for all 512 steps.
// h_{t-1} (16 b x 1024 k, 64KB) staged to smem per step via cp.async.cg,
// each kg warp-quad copies & consumes its own 16KB chunk (named barrier).
// Cross-CTA sync: per-(t, bgroup) counters, 32 producers each.
// ---------------------------------------------------------------------------
#define SW_F  (H_ * 32)          // 32768 floats
#define SH_ROW 1028              // 1024 + 4 pad (conflict-free float4)
#define SH_F  (16 * SH_ROW)      // 16448 floats
#define RED_U64 (4 * 16 * 17)    // [kg][P][b+pad]

__global__ void __launch_bounds__(512) rnn_layer_kernel(const float* __restrict__ Whh,
                                                        float* __restrict__ buf,
                                                        int* __restrict__ flags) {
    extern __shared__ __align__(16) float smem[];
    float* sW = smem;            // [k][32]
    float* sH = smem + SW_F;     // [16][1028]
    u64*  red = (u64*)(sH + SH_F);

    const int tid  = threadIdx.x;
    const int warp = tid >> 5, lane = tid & 31;
    const int ng4  = warp & 3;
    const int kg   = warp >> 2;
    const int bb   = lane & 15;
    const int kh   = lane >> 4;
    const int bg   = blockIdx.x & 3;
    const int n0   = (blockIdx.x >> 2) * 32;
    const int b0   = bg * 16;
    const int nloc = ng4 * 8;
    const int kbase = kg * 256 + kh * 128;

    // Load W slice: sW[k][j] = Whh[n0+j][k]
#pragma unroll
    for (int i = 0; i < 16; i++) {
        int v = tid + i * 512;          // 0..8191 float4s
        int j = v >> 8, k4 = v & 255;
        float4 f = __ldg((const float4*)(Whh + (size_t)(n0 + j) * H_ + k4 * 4));
        sW[(k4 * 4 + 0) * 32 + j] = f.x;
        sW[(k4 * 4 + 1) * 32 + j] = f.y;
        sW[(k4 * 4 + 2) * 32 + j] = f.z;
        sW[(k4 * 4 + 3) * 32 + j] = f.w;
    }
    __syncthreads();

    // t = 0: h_0 = tanh(pre_0) on own tile
    if (tid < 256) {
        int b = tid >> 4, P = tid & 15;
        float* addr = buf + ((size_t)(b0 + b)) * H_ + n0 + P * 2;
        float2 v = unpk(*(const u64*)addr);
        *(u64*)addr = pack2(tanhf(v.x), tanhf(v.y));
    }
    __threadfence();
    __syncthreads();
    if (tid == 0) atomicAdd(&flags[0 * 4 + bg], 1);

    const int gtid = tid & 127;   // id within kg warp-quad (warps contiguous)

    for (int t = 1; t < S_; t++) {
        // Wait for all 32 producers of h_{t-1} in our b-group
        if (tid == 0) {
            while (ld_cg_i(&flags[(t - 1) * 4 + bg]) < 32) __nanosleep(32);
        }
        __syncthreads();

        // Copy chunk kg (16 rows x 256 floats = 16KB) by this kg's 4 warps
        {
            const float* src = buf + ((size_t)(t - 1) * B_ + b0) * H_ + kg * 256;
#pragma unroll
            for (int i = 0; i < 8; i++) {
                int v = gtid + i * 128;      // 0..1023 float4s
                int r = v >> 6, c = v & 63;
                cpasync16(&sH[r * SH_ROW + kg * 256 + c * 4], src + (size_t)r * H_ + c * 4);
            }
            asm volatile("cp.async.commit_group;");
            asm volatile("cp.async.wait_group 0;");
            asm volatile("bar.sync %0, 128;" :: "r"(1 + kg) : "memory");
        }

        // Compute: 8 n x 1 b x 128 k per lane
        u64 a0 = 0, a1 = 0, a2 = 0, a3 = 0;
        const float* hrow = sH + bb * SH_ROW + kbase;
#pragma unroll 8
        for (int k4 = 0; k4 < 32; k4++) {
            float4 hv = *(const float4*)(hrow + k4 * 4);
            const float* w = sW + (size_t)(kbase + k4 * 4) * 32 + nloc;
            {
                u64 ph = pack2(hv.x, hv.x);
                ulonglong2 wa = *(const ulonglong2*)w;
                ulonglong2 wb = *(const ulonglong2*)(w + 4);
                a0 = fma2(ph, wa.x, a0); a1 = fma2(ph, wa.y, a1);
                a2 = fma2(ph, wb.x, a2); a3 = fma2(ph, wb.y, a3);
            }
            {
                u64 ph = pack2(hv.y, hv.y);
                ulonglong2 wa = *(const ulonglong2*)(w + 32);
                ulonglong2 wb = *(const ulonglong2*)(w + 36);
                a0 = fma2(ph, wa.x, a0); a1 = fma2(ph, wa.y, a1);
                a2 = fma2(ph, wb.x, a2); a3 = fma2(ph, wb.y, a3);
            }
            {
                u64 ph = pack2(hv.z, hv.z);
                ulonglong2 wa = *(const ulonglong2*)(w + 64);
                ulonglong2 wb = *(const ulonglong2*)(w + 68);
                a0 = fma2(ph, wa.x, a0); a1 = fma2(ph, wa.y, a1);
                a2 = fma2(ph, wb.x, a2); a3 = fma2(ph, wb.y, a3);
            }
            {
                u64 ph = pack2(hv.w, hv.w);
                ulonglong2 wa = *(const ulonglong2*)(w + 96);
                ulonglong2 wb = *(const ulonglong2*)(w + 100);
                a0 = fma2(ph, wa.x, a0); a1 = fma2(ph, wa.y, a1);
                a2 = fma2(ph, wb.x, a2); a3 = fma2(ph, wb.y, a3);
            }
        }

        // Fold the two k-halves within the warp
        a0 = add2(a0, __shfl_xor_sync(0xffffffffu, a0, 16));
        a1 = add2(a1, __shfl_xor_sync(0xffffffffu, a1, 16));
        a2 = add2(a2, __shfl_xor_sync(0xffffffffu, a2, 16));
        a3 = add2(a3, __shfl_xor_sync(0xffffffffu, a3, 16));

        if (kh == 0) {
            int P0 = ng4 * 4;
            red[kg * 272 + (P0 + 0) * 17 + bb] = a0;
            red[kg * 272 + (P0 + 1) * 17 + bb] = a1;
            red[kg * 272 + (P0 + 2) * 17 + bb] = a2;
            red[kg * 272 + (P0 + 3) * 17 + bb] = a3;
        }
        __syncthreads();

        // Finalize: reduce 4 kg partials + pre, tanh, store h_t
        if (tid < 256) {
            int b = tid >> 4, P = tid & 15;
            u64 s01 = add2(red[0 * 272 + P * 17 + b], red[1 * 272 + P * 17 + b]);
            u64 s23 = add2(red[2 * 272 + P * 17 + b], red[3 * 272 + P * 17 + b]);
            u64 s = add2(s01, s23);
            float* addr = buf + ((size_t)t * B_ + b0 + b) * H_ + n0 + P * 2;
            s = add2(s, *(const u64*)addr);
            float2 v = unpk(s);
            *(u64*)addr = pack2(tanhf(v.x), tanhf(v.y));
        }
        __threadfence();
        __syncthreads();
        if (tid == 0) atomicAdd(&flags[t * 4 + bg], 1);
    }
}

// ---------------------------------------------------------------------------

extern "C" void kernel_launch(void* const* d_in, const int* in_sizes, int n_in,
                              void* d_out, int out_size) {
    const float* x      = (const float*)d_in[0];
    const float* W_ih_0 = (const float*)d_in[1];
    const float* W_hh_0 = (const float*)d_in[2];
    const float* b_ih_0 = (const float*)d_in[3];
    const float* b_hh_0 = (const float*)d_in[4];
    const float* W_ih_1 = (const float*)d_in[5];
    const float* W_hh_1 = (const float*)d_in[6];
    const float* b_ih_1 = (const float*)d_in[7];
    const float* b_hh_1 = (const float*)d_in[8];
    const float* fc_w   = (const float*)d_in[9];
    const float* fc_b   = (const float*)d_in[10];
    float* out = (float*)d_out;

    float *buf0, *buf1;
    int* flags;
    cudaGetSymbolAddress((void**)&buf0, g_buf0);
    cudaGetSymbolAddress((void**)&buf1, g_buf1);
    cudaGetSymbolAddress((void**)&flags, g_flags);

    const int rnn_smem = (SW_F + SH_F) * 4 + RED_U64 * 8;   // ~205.6 KB
    static bool attr_set = false;
    if (!attr_set) {
        cudaFuncSetAttribute(rnn_layer_kernel,
                             cudaFuncAttributeMaxDynamicSharedMemorySize, rnn_smem);
        attr_set = true;
    }

    zero_flags_k<<<4, 1024>>>(flags);
    // 1. pre0[s][b][h] = x @ W_ih_0^T + (b_ih_0 + b_hh_0)
    gemm_k<I_, 0, 0><<<dim3(H_ / 128, S_), 128>>>(x, W_ih_0, b_ih_0, b_hh_0, buf0);
    // 2. layer-0 recurrence (in place)
    rnn_layer_kernel<<<128, 512, rnn_smem>>>(W_hh_0, buf0, flags);
    // 3. pre1[s][b][h] = hs0 @ W_ih_1^T + (b_ih_1 + b_hh_1)
    gemm_k<H_, 1, 0><<<dim3(H_ / 128, S_), 128>>>(buf0, W_ih_1, b_ih_1, b_hh_1, buf1);
    // 4. layer-1 recurrence (in place)
    rnn_layer_kernel<<<128, 512, rnn_smem>>>(W_hh_1, buf1, flags + S_ * 4);
    // 5. out[b][s][o] = hs1 @ fc_w^T + fc_b
    gemm_k<H_, 1, 1><<<dim3(O_ / 128, S_), 128>>>(buf1, fc_w, fc_b, nullptr, out);
}